// round 15
// baseline (speedup 1.0000x reference)
#include <cuda_runtime.h>
#include <cstdint>
#include <cstddef>

#define RLA_EPS 1e-6f

__device__ __forceinline__ float elu1(float x) {
    return x > 0.0f ? x + 1.0f : __expf(x);
}

__device__ __forceinline__ uint32_t s2u(const void* p) {
    uint32_t a;
    asm("{ .reg .u64 t; cvta.to.shared.u64 t, %1; cvt.u32.u64 %0, t; }"
        : "=r"(a) : "l"(p));
    return a;
}

__device__ __forceinline__ void mbar_init(uint32_t m, uint32_t cnt) {
    asm volatile("mbarrier.init.shared.b64 [%0], %1;" :: "r"(m), "r"(cnt) : "memory");
}
__device__ __forceinline__ void mbar_expect(uint32_t m, uint32_t bytes) {
    asm volatile("mbarrier.arrive.expect_tx.shared.b64 _, [%0], %1;"
                 :: "r"(m), "r"(bytes) : "memory");
}
__device__ __forceinline__ void mbar_wait(uint32_t m, uint32_t parity) {
    asm volatile(
        "{\n\t.reg .pred P;\n\t"
        "W%=:\n\t"
        "mbarrier.try_wait.parity.acquire.cta.shared::cta.b64 P, [%0], %1;\n\t"
        "@!P bra W%=;\n\t"
        "}\n"
        :: "r"(m), "r"(parity) : "memory");
}
// TMA bulk load with L2 evict-first hint: streaming reads (zero reuse) must
// not evict the dirty write stream from L2 — keep L2 as a write-coalescing
// buffer so writebacks drain in large same-direction batches.
__device__ __forceinline__ void bulk_ld_ef(uint32_t dst, const void* src,
                                           uint32_t bytes, uint32_t mbar) {
    asm volatile(
        "{\n\t.reg .b64 pol;\n\t"
        "createpolicy.fractional.L2::evict_first.b64 pol, 1.0;\n\t"
        "cp.async.bulk.shared::cta.global.mbarrier::complete_tx::bytes.L2::cache_hint"
        " [%0], [%1], %2, [%3], pol;\n\t}"
        :: "r"(dst), "l"(src), "r"(bytes), "r"(mbar) : "memory");
}
__device__ __forceinline__ void bulk_st(void* dst, uint32_t src, uint32_t bytes) {
    asm volatile("cp.async.bulk.global.shared::cta.bulk_group [%0], [%1], %2;"
                 :: "l"(dst), "r"(src), "r"(bytes) : "memory");
}

// ============== TMA-pipelined kernel, specialized D=256, M=256 ==============
// One CTA per (b,n), 256 threads, occupancy 2 (96KB dynamic smem).
// 8 chunks of 32 rows (32KB) through a 3-buffer smem ring; next TMA load
// issued right after the mbar wait (round-11 champion structure).
// NEW: loads carry an L2 evict-first cache hint (see bulk_ld_ef).
__global__ __launch_bounds__(256, 2)
void rla_tma_kernel(const float* __restrict__ q,
                    const float* __restrict__ k,
                    const float* __restrict__ v,
                    const float* __restrict__ Si,
                    const float* __restrict__ Zi,
                    float* __restrict__ outV,
                    float* __restrict__ outSi,
                    float* __restrict__ outZi)
{
    constexpr int D = 256, M = 256, M4 = 64;
    constexpr int CROWS = 32;                 // rows per chunk
    constexpr int NCHUNK = D / CROWS;         // 8
    constexpr int NBUF = 3;
    constexpr uint32_t CBYTES = CROWS * M4 * 16;   // 32768
    constexpr int CF4 = CROWS * M4;                // 2048 float4

    extern __shared__ __align__(128) float4 dyn[];  // NBUF * CF4 = 96KB

    __shared__ float sQ[D];
    __shared__ float sK[D];
    __shared__ float swred[8];
    __shared__ float sZ;
    __shared__ float4 sacc[256];
    __shared__ uint64_t mbars[NBUF];

    const int bn  = blockIdx.x;
    const int tid = threadIdx.x;

    const size_t rowD = (size_t)bn * D;
    const size_t rowM = (size_t)bn * M;
    const size_t tile = (size_t)bn * D * M;

    const float4* gsrc = (const float4*)(Si    + tile);
    float4*       gdst = (float4*)      (outSi + tile);

    // ---- init barriers, kick off prologue loads (chunks 0,1) ----
    if (tid == 0) {
        #pragma unroll
        for (int b = 0; b < NBUF; b++) mbar_init(s2u(&mbars[b]), 1);
    }
    __syncthreads();
    if (tid == 0) {
        #pragma unroll
        for (int c = 0; c < NBUF - 1; c++) {
            uint32_t m = s2u(&mbars[c]);
            mbar_expect(m, CBYTES);
            bulk_ld_ef(s2u(&dyn[c * CF4]), gsrc + (size_t)c * CF4, CBYTES, m);
        }
    }

    // ---- phase 1: feature maps + normalizer (overlaps prologue loads) ----
    const int lane32 = tid & 31;
    const int warp   = tid >> 5;
    {
        const int d = tid;  // D == blockDim.x
        float Qd = elu1(q[rowD + d]);
        float Kd = elu1(k[rowD + d]);
        float zn = Zi[rowD + d] + Kd;
        outZi[rowD + d] = zn;
        sQ[d] = Qd;
        sK[d] = Kd;
        float part = Qd * zn;
        #pragma unroll
        for (int o = 16; o > 0; o >>= 1)
            part += __shfl_down_sync(0xffffffffu, part, o);
        if (lane32 == 0) swred[warp] = part;
    }
    __syncthreads();
    if (tid == 0) {
        float s = 0.0f;
        #pragma unroll
        for (int w = 0; w < 8; w++) s += swred[w];
        sZ = 1.0f / (s + RLA_EPS);
    }
    __syncthreads();
    const float Z = sZ;

    // ---- pipelined main loop ----
    const int lane = tid & 63;     // float4 column
    const int ty   = tid >> 6;     // 0..3

    const float4 v4 = ((const float4*)(v + rowM))[lane];
    float4 acc = make_float4(0.f, 0.f, 0.f, 0.f);

    for (int c = 0; c < NCHUNK; c++) {
        const int b   = c % NBUF;
        const int par = (c / NBUF) & 1;
        mbar_wait(s2u(&mbars[b]), par);

        // Issue next load EARLY: buffer (c+2)%3 == (c-1)%3; all threads
        // finished reading chunk c-1 before last iteration's syncthreads,
        // and wait_group.read 0 drains store c-1's smem reads (only store
        // c-1 can be pending here; c-2 was drained in iteration c-1).
        if (tid == 0) {
            const int cn = c + NBUF - 1;          // chunk c+2
            if (cn < NCHUNK) {
                asm volatile("cp.async.bulk.wait_group.read 0;" ::: "memory");
                const int nb = cn % NBUF;
                uint32_t m = s2u(&mbars[nb]);
                mbar_expect(m, CBYTES);
                bulk_ld_ef(s2u(&dyn[nb * CF4]), gsrc + (size_t)cn * CF4, CBYTES, m);
            }
        }

        float4* B = &dyn[b * CF4];
        #pragma unroll
        for (int j = 0; j < CROWS / 4; j++) {
            const int r = ty + 4 * j;
            const int d = c * CROWS + r;
            float4 s = B[r * M4 + lane];
            const float kd = sK[d];
            const float qd = sQ[d];
            s.x = fmaf(kd, v4.x, s.x);
            s.y = fmaf(kd, v4.y, s.y);
            s.z = fmaf(kd, v4.z, s.z);
            s.w = fmaf(kd, v4.w, s.w);
            B[r * M4 + lane] = s;
            acc.x = fmaf(qd, s.x, acc.x);
            acc.y = fmaf(qd, s.y, acc.y);
            acc.z = fmaf(qd, s.z, acc.z);
            acc.w = fmaf(qd, s.w, acc.w);
        }
        __syncthreads();

        if (tid == 0) {
            asm volatile("fence.proxy.async.shared::cta;" ::: "memory");
            bulk_st(gdst + (size_t)c * CF4, s2u(&dyn[b * CF4]), CBYTES);
            asm volatile("cp.async.bulk.commit_group;" ::: "memory");
        }
    }

    // ---- V reduction across the 4 d-subgroups ----
    sacc[tid] = acc;
    __syncthreads();
    if (ty == 0) {
        float4 a0 = sacc[lane];
        float4 a1 = sacc[lane + 64];
        float4 a2 = sacc[lane + 128];
        float4 a3 = sacc[lane + 192];
        float4 out;
        out.x = Z * (a0.x + a1.x + a2.x + a3.x);
        out.y = Z * (a0.y + a1.y + a2.y + a3.y);
        out.z = Z * (a0.z + a1.z + a2.z + a3.z);
        out.w = Z * (a0.w + a1.w + a2.w + a3.w);
        ((float4*)(outV + rowM))[lane] = out;
    }

    // ---- drain pending TMA stores before CTA exit ----
    if (tid == 0) {
        asm volatile("cp.async.bulk.wait_group.read 0;" ::: "memory");
    }
    __syncthreads();
}

// ===================== generic fallback (round-1 structure) =================
__global__ __launch_bounds__(256, 8)
void rla_generic_kernel(const float* __restrict__ q,
                        const float* __restrict__ k,
                        const float* __restrict__ v,
                        const float* __restrict__ Si,
                        const float* __restrict__ Zi,
                        float* __restrict__ outV,
                        float* __restrict__ outSi,
                        float* __restrict__ outZi,
                        int D, int M)
{
    const int bn  = blockIdx.x;
    const int tid = threadIdx.x;

    __shared__ float sQ[1024];
    __shared__ float sK[1024];
    __shared__ float sred[256];
    __shared__ float sZ;
    __shared__ float4 sacc[256];

    const size_t rowD = (size_t)bn * D;
    const size_t rowM = (size_t)bn * M;
    const size_t tile = (size_t)bn * D * M;

    float part = 0.0f;
    for (int d = tid; d < D; d += blockDim.x) {
        float Qd = elu1(q[rowD + d]);
        float Kd = elu1(k[rowD + d]);
        float zn = Zi[rowD + d] + Kd;
        outZi[rowD + d] = zn;
        sQ[d] = Qd;
        sK[d] = Kd;
        part += Qd * zn;
    }
    sred[tid] = part;
    __syncthreads();
    #pragma unroll
    for (int s = 128; s > 0; s >>= 1) {
        if (tid < s) sred[tid] += sred[tid + s];
        __syncthreads();
    }
    if (tid == 0) sZ = 1.0f / (sred[0] + RLA_EPS);
    __syncthreads();
    const float Z = sZ;

    const int M4   = M >> 2;
    const int lane = tid & 63;
    const int ty   = tid >> 6;

    const float4* Si4 = (const float4*)(Si    + tile);
    float4*       So4 = (float4*)      (outSi + tile);
    const float4* v4p = (const float4*)(v     + rowM);
    float4*       V4  = (float4*)      (outV  + rowM);

    for (int m0 = 0; m0 < M4; m0 += 64) {
        const int m4 = m0 + lane;
        const bool act = (m4 < M4);
        float4 v4 = make_float4(0.f, 0.f, 0.f, 0.f);
        if (act) v4 = v4p[m4];
        float4 acc = make_float4(0.f, 0.f, 0.f, 0.f);
        if (act) {
            #pragma unroll 8
            for (int d = ty; d < D; d += 4) {
                const size_t idx = (size_t)d * M4 + m4;
                float4 s = __ldcs(&Si4[idx]);
                const float kd = sK[d];
                const float qd = sQ[d];
                s.x = fmaf(kd, v4.x, s.x);
                s.y = fmaf(kd, v4.y, s.y);
                s.z = fmaf(kd, v4.z, s.z);
                s.w = fmaf(kd, v4.w, s.w);
                __stcs(&So4[idx], s);
                acc.x = fmaf(qd, s.x, acc.x);
                acc.y = fmaf(qd, s.y, acc.y);
                acc.z = fmaf(qd, s.z, acc.z);
                acc.w = fmaf(qd, s.w, acc.w);
            }
        }
        sacc[tid] = acc;
        __syncthreads();
        if (ty == 0 && act) {
            float4 a0 = sacc[lane];
            float4 a1 = sacc[lane + 64];
            float4 a2 = sacc[lane + 128];
            float4 a3 = sacc[lane + 192];
            float4 out;
            out.x = Z * (a0.x + a1.x + a2.x + a3.x);
            out.y = Z * (a0.y + a1.y + a2.y + a3.y);
            out.z = Z * (a0.z + a1.z + a2.z + a3.z);
            out.w = Z * (a0.w + a1.w + a2.w + a3.w);
            V4[m4] = out;
        }
        __syncthreads();
    }
}

extern "C" void kernel_launch(void* const* d_in, const int* in_sizes, int n_in,
                              void* d_out, int out_size)
{
    const float* q  = (const float*)d_in[0];
    const float* k  = (const float*)d_in[1];
    const float* v  = (const float*)d_in[2];
    const float* Si = (const float*)d_in[3];
    const float* Zi = (const float*)d_in[4];

    const long long nQ  = in_sizes[0];  // BN * D
    const long long nV  = in_sizes[2];  // BN * M
    const long long nSi = in_sizes[3];  // BN * D * M

    const int D  = (int)(nSi / nV);
    const int M  = (int)(nSi / nQ);
    const int BN = (int)(nQ / D);

    float* out   = (float*)d_out;
    float* outV  = out;                 // [BN, M]
    float* outSi = out + nV;            // [BN, D, M]
    float* outZi = out + nV + nSi;      // [BN, D]

    if (D == 256 && M == 256) {
        cudaFuncSetAttribute(rla_tma_kernel,
                             cudaFuncAttributeMaxDynamicSharedMemorySize, 98304);
        rla_tma_kernel<<<BN, 256, 98304>>>(q, k, v, Si, Zi, outV, outSi, outZi);
    } else {
        rla_generic_kernel<<<BN, 256>>>(q, k, v, Si, Zi, outV, outSi, outZi, D, M);
    }
}

// round 16
// speedup vs baseline: 1.0041x; 1.0041x over previous
#include <cuda_runtime.h>
#include <cstdint>
#include <cstddef>

#define RLA_EPS 1e-6f

__device__ __forceinline__ float elu1(float x) {
    return x > 0.0f ? x + 1.0f : __expf(x);
}

__device__ __forceinline__ uint32_t s2u(const void* p) {
    uint32_t a;
    asm("{ .reg .u64 t; cvta.to.shared.u64 t, %1; cvt.u32.u64 %0, t; }"
        : "=r"(a) : "l"(p));
    return a;
}

__device__ __forceinline__ void mbar_init(uint32_t m, uint32_t cnt) {
    asm volatile("mbarrier.init.shared.b64 [%0], %1;" :: "r"(m), "r"(cnt) : "memory");
}
__device__ __forceinline__ void mbar_expect(uint32_t m, uint32_t bytes) {
    asm volatile("mbarrier.arrive.expect_tx.shared.b64 _, [%0], %1;"
                 :: "r"(m), "r"(bytes) : "memory");
}
__device__ __forceinline__ void mbar_wait(uint32_t m, uint32_t parity) {
    asm volatile(
        "{\n\t.reg .pred P;\n\t"
        "W%=:\n\t"
        "mbarrier.try_wait.parity.acquire.cta.shared::cta.b64 P, [%0], %1;\n\t"
        "@!P bra W%=;\n\t"
        "}\n"
        :: "r"(m), "r"(parity) : "memory");
}
__device__ __forceinline__ void bulk_ld(uint32_t dst, const void* src,
                                        uint32_t bytes, uint32_t mbar) {
    asm volatile(
        "cp.async.bulk.shared::cta.global.mbarrier::complete_tx::bytes [%0], [%1], %2, [%3];"
        :: "r"(dst), "l"(src), "r"(bytes), "r"(mbar) : "memory");
}
__device__ __forceinline__ void bulk_st(void* dst, uint32_t src, uint32_t bytes) {
    asm volatile("cp.async.bulk.global.shared::cta.bulk_group [%0], [%1], %2;"
                 :: "l"(dst), "r"(src), "r"(bytes) : "memory");
}

// ============== TMA-pipelined kernel, specialized D=256, M=256 ==============
// FINAL (round-11 champion configuration, plateau-verified):
// One CTA per (b,n), 256 threads, occupancy 2 (96KB dynamic smem).
// 8 chunks of 32 rows (32KB DRAM bursts — measured optimum: 16KB and 64KB
// are both slower) through a 3-buffer smem ring. The load for chunk c+2 is
// issued right after mbar_wait(c) returns (measured optimum vs after-store
// and before-wait). Cache hints / prefetch / persistence all measured
// neutral-or-worse; DRAM efficiency 79.7% is the controller floor for this
// 50/50 read/write mix.
__global__ __launch_bounds__(256, 2)
void rla_tma_kernel(const float* __restrict__ q,
                    const float* __restrict__ k,
                    const float* __restrict__ v,
                    const float* __restrict__ Si,
                    const float* __restrict__ Zi,
                    float* __restrict__ outV,
                    float* __restrict__ outSi,
                    float* __restrict__ outZi)
{
    constexpr int D = 256, M = 256, M4 = 64;
    constexpr int CROWS = 32;                 // rows per chunk
    constexpr int NCHUNK = D / CROWS;         // 8
    constexpr int NBUF = 3;
    constexpr uint32_t CBYTES = CROWS * M4 * 16;   // 32768
    constexpr int CF4 = CROWS * M4;                // 2048 float4

    extern __shared__ __align__(128) float4 dyn[];  // NBUF * CF4 = 96KB

    __shared__ float sQ[D];
    __shared__ float sK[D];
    __shared__ float swred[8];
    __shared__ float sZ;
    __shared__ float4 sacc[256];
    __shared__ uint64_t mbars[NBUF];

    const int bn  = blockIdx.x;
    const int tid = threadIdx.x;

    const size_t rowD = (size_t)bn * D;
    const size_t rowM = (size_t)bn * M;
    const size_t tile = (size_t)bn * D * M;

    const float4* gsrc = (const float4*)(Si    + tile);
    float4*       gdst = (float4*)      (outSi + tile);

    // ---- init barriers, kick off prologue loads (chunks 0,1) ----
    if (tid == 0) {
        #pragma unroll
        for (int b = 0; b < NBUF; b++) mbar_init(s2u(&mbars[b]), 1);
    }
    __syncthreads();
    if (tid == 0) {
        #pragma unroll
        for (int c = 0; c < NBUF - 1; c++) {
            uint32_t m = s2u(&mbars[c]);
            mbar_expect(m, CBYTES);
            bulk_ld(s2u(&dyn[c * CF4]), gsrc + (size_t)c * CF4, CBYTES, m);
        }
    }

    // ---- phase 1: feature maps + normalizer (overlaps prologue loads) ----
    const int lane32 = tid & 31;
    const int warp   = tid >> 5;
    {
        const int d = tid;  // D == blockDim.x
        float Qd = elu1(q[rowD + d]);
        float Kd = elu1(k[rowD + d]);
        float zn = Zi[rowD + d] + Kd;
        outZi[rowD + d] = zn;
        sQ[d] = Qd;
        sK[d] = Kd;
        float part = Qd * zn;
        #pragma unroll
        for (int o = 16; o > 0; o >>= 1)
            part += __shfl_down_sync(0xffffffffu, part, o);
        if (lane32 == 0) swred[warp] = part;
    }
    __syncthreads();
    if (tid == 0) {
        float s = 0.0f;
        #pragma unroll
        for (int w = 0; w < 8; w++) s += swred[w];
        sZ = 1.0f / (s + RLA_EPS);
    }
    __syncthreads();
    const float Z = sZ;

    // ---- pipelined main loop ----
    const int lane = tid & 63;     // float4 column
    const int ty   = tid >> 6;     // 0..3

    const float4 v4 = ((const float4*)(v + rowM))[lane];
    float4 acc = make_float4(0.f, 0.f, 0.f, 0.f);

    for (int c = 0; c < NCHUNK; c++) {
        const int b   = c % NBUF;
        const int par = (c / NBUF) & 1;
        mbar_wait(s2u(&mbars[b]), par);

        // Issue next load EARLY: buffer (c+2)%3 == (c-1)%3; all threads
        // finished reading chunk c-1 before last iteration's syncthreads,
        // and wait_group.read 0 drains store c-1's smem reads (only store
        // c-1 can be pending here; c-2 was drained in iteration c-1).
        if (tid == 0) {
            const int cn = c + NBUF - 1;          // chunk c+2
            if (cn < NCHUNK) {
                asm volatile("cp.async.bulk.wait_group.read 0;" ::: "memory");
                const int nb = cn % NBUF;
                uint32_t m = s2u(&mbars[nb]);
                mbar_expect(m, CBYTES);
                bulk_ld(s2u(&dyn[nb * CF4]), gsrc + (size_t)cn * CF4, CBYTES, m);
            }
        }

        float4* B = &dyn[b * CF4];
        #pragma unroll
        for (int j = 0; j < CROWS / 4; j++) {
            const int r = ty + 4 * j;
            const int d = c * CROWS + r;
            float4 s = B[r * M4 + lane];
            const float kd = sK[d];
            const float qd = sQ[d];
            s.x = fmaf(kd, v4.x, s.x);
            s.y = fmaf(kd, v4.y, s.y);
            s.z = fmaf(kd, v4.z, s.z);
            s.w = fmaf(kd, v4.w, s.w);
            B[r * M4 + lane] = s;
            acc.x = fmaf(qd, s.x, acc.x);
            acc.y = fmaf(qd, s.y, acc.y);
            acc.z = fmaf(qd, s.z, acc.z);
            acc.w = fmaf(qd, s.w, acc.w);
        }
        __syncthreads();

        if (tid == 0) {
            asm volatile("fence.proxy.async.shared::cta;" ::: "memory");
            bulk_st(gdst + (size_t)c * CF4, s2u(&dyn[b * CF4]), CBYTES);
            asm volatile("cp.async.bulk.commit_group;" ::: "memory");
        }
    }

    // ---- V reduction across the 4 d-subgroups ----
    sacc[tid] = acc;
    __syncthreads();
    if (ty == 0) {
        float4 a0 = sacc[lane];
        float4 a1 = sacc[lane + 64];
        float4 a2 = sacc[lane + 128];
        float4 a3 = sacc[lane + 192];
        float4 out;
        out.x = Z * (a0.x + a1.x + a2.x + a3.x);
        out.y = Z * (a0.y + a1.y + a2.y + a3.y);
        out.z = Z * (a0.z + a1.z + a2.z + a3.z);
        out.w = Z * (a0.w + a1.w + a2.w + a3.w);
        ((float4*)(outV + rowM))[lane] = out;
    }

    // ---- drain pending TMA stores before CTA exit ----
    if (tid == 0) {
        asm volatile("cp.async.bulk.wait_group.read 0;" ::: "memory");
    }
    __syncthreads();
}

// ===================== generic fallback (round-1 structure) =================
__global__ __launch_bounds__(256, 8)
void rla_generic_kernel(const float* __restrict__ q,
                        const float* __restrict__ k,
                        const float* __restrict__ v,
                        const float* __restrict__ Si,
                        const float* __restrict__ Zi,
                        float* __restrict__ outV,
                        float* __restrict__ outSi,
                        float* __restrict__ outZi,
                        int D, int M)
{
    const int bn  = blockIdx.x;
    const int tid = threadIdx.x;

    __shared__ float sQ[1024];
    __shared__ float sK[1024];
    __shared__ float sred[256];
    __shared__ float sZ;
    __shared__ float4 sacc[256];

    const size_t rowD = (size_t)bn * D;
    const size_t rowM = (size_t)bn * M;
    const size_t tile = (size_t)bn * D * M;

    float part = 0.0f;
    for (int d = tid; d < D; d += blockDim.x) {
        float Qd = elu1(q[rowD + d]);
        float Kd = elu1(k[rowD + d]);
        float zn = Zi[rowD + d] + Kd;
        outZi[rowD + d] = zn;
        sQ[d] = Qd;
        sK[d] = Kd;
        part += Qd * zn;
    }
    sred[tid] = part;
    __syncthreads();
    #pragma unroll
    for (int s = 128; s > 0; s >>= 1) {
        if (tid < s) sred[tid] += sred[tid + s];
        __syncthreads();
    }
    if (tid == 0) sZ = 1.0f / (sred[0] + RLA_EPS);
    __syncthreads();
    const float Z = sZ;

    const int M4   = M >> 2;
    const int lane = tid & 63;
    const int ty   = tid >> 6;

    const float4* Si4 = (const float4*)(Si    + tile);
    float4*       So4 = (float4*)      (outSi + tile);
    const float4* v4p = (const float4*)(v     + rowM);
    float4*       V4  = (float4*)      (outV  + rowM);

    for (int m0 = 0; m0 < M4; m0 += 64) {
        const int m4 = m0 + lane;
        const bool act = (m4 < M4);
        float4 v4 = make_float4(0.f, 0.f, 0.f, 0.f);
        if (act) v4 = v4p[m4];
        float4 acc = make_float4(0.f, 0.f, 0.f, 0.f);
        if (act) {
            #pragma unroll 8
            for (int d = ty; d < D; d += 4) {
                const size_t idx = (size_t)d * M4 + m4;
                float4 s = __ldcs(&Si4[idx]);
                const float kd = sK[d];
                const float qd = sQ[d];
                s.x = fmaf(kd, v4.x, s.x);
                s.y = fmaf(kd, v4.y, s.y);
                s.z = fmaf(kd, v4.z, s.z);
                s.w = fmaf(kd, v4.w, s.w);
                __stcs(&So4[idx], s);
                acc.x = fmaf(qd, s.x, acc.x);
                acc.y = fmaf(qd, s.y, acc.y);
                acc.z = fmaf(qd, s.z, acc.z);
                acc.w = fmaf(qd, s.w, acc.w);
            }
        }
        sacc[tid] = acc;
        __syncthreads();
        if (ty == 0 && act) {
            float4 a0 = sacc[lane];
            float4 a1 = sacc[lane + 64];
            float4 a2 = sacc[lane + 128];
            float4 a3 = sacc[lane + 192];
            float4 out;
            out.x = Z * (a0.x + a1.x + a2.x + a3.x);
            out.y = Z * (a0.y + a1.y + a2.y + a3.y);
            out.z = Z * (a0.z + a1.z + a2.z + a3.z);
            out.w = Z * (a0.w + a1.w + a2.w + a3.w);
            V4[m4] = out;
        }
        __syncthreads();
    }
}

extern "C" void kernel_launch(void* const* d_in, const int* in_sizes, int n_in,
                              void* d_out, int out_size)
{
    const float* q  = (const float*)d_in[0];
    const float* k  = (const float*)d_in[1];
    const float* v  = (const float*)d_in[2];
    const float* Si = (const float*)d_in[3];
    const float* Zi = (const float*)d_in[4];

    const long long nQ  = in_sizes[0];  // BN * D
    const long long nV  = in_sizes[2];  // BN * M
    const long long nSi = in_sizes[3];  // BN * D * M

    const int D  = (int)(nSi / nV);
    const int M  = (int)(nSi / nQ);
    const int BN = (int)(nQ / D);

    float* out   = (float*)d_out;
    float* outV  = out;                 // [BN, M]
    float* outSi = out + nV;            // [BN, D, M]
    float* outZi = out + nV + nSi;      // [BN, D]

    if (D == 256 && M == 256) {
        cudaFuncSetAttribute(rla_tma_kernel,
                             cudaFuncAttributeMaxDynamicSharedMemorySize, 98304);
        rla_tma_kernel<<<BN, 256, 98304>>>(q, k, v, Si, Zi, outV, outSi, outZi);
    } else {
        rla_generic_kernel<<<BN, 256>>>(q, k, v, Si, Zi, outV, outSi, outZi, D, M);
    }
}